// round 1
// baseline (speedup 1.0000x reference)
#include <cuda_runtime.h>
#include <cstdint>

// GRU-D with diagonal weights: fully elementwise recurrence.
// One thread owns one (b, f) chain for all T=512 steps.
// Memory-bound: 537 MB streamed -> ~67 us floor at 8 TB/s.

#define TT 512
#define BB 256
#define FF 256
#define BF (BB * FF)
#define UNROLL 8
#define BLK 64

__device__ __forceinline__ float sigmoid_f(float v) {
    // rcp.approx + ex2.approx path: ~1e-7 rel err, 2 MUFU
    return __fdividef(1.0f, 1.0f + __expf(-v));
}

__device__ __forceinline__ float tanh_f(float v) {
    // tanh(x) = 2/(1+exp(-2x)) - 1  (avoids tanh.approx's 5e-4 error)
    return __fdividef(2.0f, 1.0f + __expf(-2.0f * v)) - 1.0f;
}

__global__ void __launch_bounds__(BLK) grud_kernel(
    const float* __restrict__ X,
    const float* __restrict__ Mask,
    const float* __restrict__ Delta,
    const float* __restrict__ x_mean,
    const float* __restrict__ w_dg_x, const float* __restrict__ b_dg_x,
    const float* __restrict__ w_dg_h, const float* __restrict__ b_dg_h,
    const float* __restrict__ w_xz,  const float* __restrict__ u_hz, const float* __restrict__ b_z,
    const float* __restrict__ w_xr,  const float* __restrict__ u_hr, const float* __restrict__ b_r,
    const float* __restrict__ w_xh,  const float* __restrict__ u_hh,
    const float* __restrict__ v_mh,  const float* __restrict__ b_h,
    float* __restrict__ out,        // [B, T, F]
    float* __restrict__ out_last)   // [B, F] or nullptr
{
    const int tid = blockIdx.x * BLK + threadIdx.x;
    const int f = tid & (FF - 1);
    const int b = tid >> 8;

    // Per-feature scalars (read once; tiny, L2-resident)
    const float xm   = x_mean[f];
    const float wdgx = w_dg_x[f], bdgx = b_dg_x[f];
    const float wdgh = w_dg_h[f], bdgh = b_dg_h[f];
    const float wxz  = w_xz[f],  uhz = u_hz[f], bz = b_z[f];
    const float wxr  = w_xr[f],  uhr = u_hr[f], br = b_r[f];
    const float wxh  = w_xh[f],  uhh = u_hh[f];
    const float vmh  = v_mh[f],  bh  = b_h[f];

    const float* xp = X     + (size_t)b * FF + f;
    const float* mp = Mask  + (size_t)b * FF + f;
    const float* dp = Delta + (size_t)b * FF + f;
    float* op = out + (size_t)b * TT * FF + f;

    float h = 0.0f;

    #pragma unroll 1
    for (int t0 = 0; t0 < TT; t0 += UNROLL) {
        // Batch the loads: 24 independent LDGs in flight per thread-group
        // before any h-dependent compute (MLP for DRAM latency hiding).
        float xv[UNROLL], mv[UNROLL], dv[UNROLL];
        #pragma unroll
        for (int u = 0; u < UNROLL; ++u) {
            const size_t off = (size_t)(t0 + u) * BF;
            xv[u] = __ldcs(xp + off);   // streaming: evict-first
            mv[u] = __ldcs(mp + off);
            dv[u] = __ldcs(dp + off);
        }
        #pragma unroll
        for (int u = 0; u < UNROLL; ++u) {
            float x = xv[u], m = mv[u], d = dv[u];

            float gx = __expf(-fmaxf(0.0f, fmaf(wdgx, d, bdgx)));
            float gh = __expf(-fmaxf(0.0f, fmaf(wdgh, d, bdgh)));

            // x = m*x + (1-m)*(gx*x + (1-gx)*xm)
            float ximp = fmaf(gx, x, (1.0f - gx) * xm);
            x = fmaf(m, x, (1.0f - m) * ximp);

            h = gh * h;

            float z  = sigmoid_f(fmaf(wxz, x, fmaf(uhz, h, bz)));
            float r  = sigmoid_f(fmaf(wxr, x, fmaf(uhr, h, br)));
            float ht = tanh_f(fmaf(wxh, x, fmaf(uhh, r * h, fmaf(vmh, m, bh))));

            // h = (1-z)*h + z*ht = h + z*(ht - h)
            h = fmaf(z, ht - h, h);

            __stcs(op + (size_t)(t0 + u) * FF, h);   // streaming store
        }
    }

    if (out_last != nullptr) {
        out_last[(size_t)b * FF + f] = h;
    }
}

extern "C" void kernel_launch(void* const* d_in, const int* in_sizes, int n_in,
                              void* d_out, int out_size) {
    const float* X      = (const float*)d_in[0];
    const float* Mask   = (const float*)d_in[1];
    const float* Delta  = (const float*)d_in[2];
    const float* x_mean = (const float*)d_in[3];
    const float* w_dg_x = (const float*)d_in[4];
    const float* b_dg_x = (const float*)d_in[5];
    const float* w_dg_h = (const float*)d_in[6];
    const float* b_dg_h = (const float*)d_in[7];
    const float* w_xz   = (const float*)d_in[8];
    const float* u_hz   = (const float*)d_in[9];
    const float* b_z    = (const float*)d_in[10];
    const float* w_xr   = (const float*)d_in[11];
    const float* u_hr   = (const float*)d_in[12];
    const float* b_r    = (const float*)d_in[13];
    const float* w_xh   = (const float*)d_in[14];
    const float* u_hh   = (const float*)d_in[15];
    const float* v_mh   = (const float*)d_in[16];
    const float* b_h    = (const float*)d_in[17];

    float* out = (float*)d_out;
    // Output = hidden_states [B,T,F] (+ last [B,F] if the harness packs the tuple)
    const long long hs_elems = (long long)BB * TT * FF;
    float* out_last = ((long long)out_size >= hs_elems + (long long)BB * FF)
                          ? out + hs_elems : nullptr;

    grud_kernel<<<BF / BLK, BLK>>>(X, Mask, Delta, x_mean,
                                   w_dg_x, b_dg_x, w_dg_h, b_dg_h,
                                   w_xz, u_hz, b_z,
                                   w_xr, u_hr, b_r,
                                   w_xh, u_hh, v_mh, b_h,
                                   out, out_last);
}

// round 2
// speedup vs baseline: 1.8212x; 1.8212x over previous
#include <cuda_runtime.h>
#include <cstdint>

// GRU-D diagonal recurrence. One thread = one (b,f) chain, T=512 steps.
// R2: software-pipelined double buffering (loads of batch N+1 overlap compute
// of batch N) + MUFU.TANH for all three nonlinearities (shorter dep chain).

#define TT 512
#define BB 256
#define FF 256
#define BF (BB * FF)
#define UNROLL 8
#define BLK 64

__device__ __forceinline__ float tanh_approx(float v) {
    float r;
    asm("tanh.approx.f32 %0, %1;" : "=f"(r) : "f"(v));
    return r;
}

__device__ __forceinline__ float sigmoid_f(float v) {
    // sigma(v) = 0.5*tanh(0.5v) + 0.5  -> 1 MUFU + 2 FMA
    return fmaf(0.5f, tanh_approx(0.5f * v), 0.5f);
}

struct Params {
    float xm, wdgx, bdgx, wdgh, bdgh;
    float wxz, uhz, bz, wxr, uhr, br, wxh, uhh, vmh, bh;
};

__global__ void __launch_bounds__(BLK) grud_kernel(
    const float* __restrict__ X,
    const float* __restrict__ Mask,
    const float* __restrict__ Delta,
    const float* __restrict__ x_mean,
    const float* __restrict__ w_dg_x, const float* __restrict__ b_dg_x,
    const float* __restrict__ w_dg_h, const float* __restrict__ b_dg_h,
    const float* __restrict__ w_xz,  const float* __restrict__ u_hz, const float* __restrict__ b_z,
    const float* __restrict__ w_xr,  const float* __restrict__ u_hr, const float* __restrict__ b_r,
    const float* __restrict__ w_xh,  const float* __restrict__ u_hh,
    const float* __restrict__ v_mh,  const float* __restrict__ b_h,
    float* __restrict__ out,        // [B, T, F]
    float* __restrict__ out_last)   // [B, F] or nullptr
{
    const int tid = blockIdx.x * BLK + threadIdx.x;
    const int f = tid & (FF - 1);
    const int b = tid >> 8;

    Params p;
    p.xm   = x_mean[f];
    p.wdgx = w_dg_x[f]; p.bdgx = b_dg_x[f];
    p.wdgh = w_dg_h[f]; p.bdgh = b_dg_h[f];
    p.wxz  = w_xz[f];   p.uhz  = u_hz[f]; p.bz = b_z[f];
    p.wxr  = w_xr[f];   p.uhr  = u_hr[f]; p.br = b_r[f];
    p.wxh  = w_xh[f];   p.uhh  = u_hh[f];
    p.vmh  = v_mh[f];   p.bh   = b_h[f];

    const float* xp = X     + (size_t)b * FF + f;
    const float* mp = Mask  + (size_t)b * FF + f;
    const float* dp = Delta + (size_t)b * FF + f;
    float* op = out + (size_t)b * TT * FF + f;

    float h = 0.0f;

    float xa[UNROLL], ma[UNROLL], da[UNROLL];
    float xb[UNROLL], mb[UNROLL], db[UNROLL];

    // ---- helpers as lambdas (inlined) ----
    auto load_batch = [&](int t0, float* xv, float* mv, float* dv) {
        #pragma unroll
        for (int u = 0; u < UNROLL; ++u) {
            const size_t off = (size_t)(t0 + u) * BF;
            xv[u] = __ldcs(xp + off);
            mv[u] = __ldcs(mp + off);
            dv[u] = __ldcs(dp + off);
        }
    };
    auto compute_batch = [&](int t0, const float* xv, const float* mv, const float* dv) {
        #pragma unroll
        for (int u = 0; u < UNROLL; ++u) {
            float x = xv[u], m = mv[u], d = dv[u];

            float gx = __expf(-fmaxf(0.0f, fmaf(p.wdgx, d, p.bdgx)));
            float gh = __expf(-fmaxf(0.0f, fmaf(p.wdgh, d, p.bdgh)));

            float ximp = fmaf(gx, x, (1.0f - gx) * p.xm);
            x = fmaf(m, x, (1.0f - m) * ximp);

            h = gh * h;

            float z  = sigmoid_f(fmaf(p.wxz, x, fmaf(p.uhz, h, p.bz)));
            float r  = sigmoid_f(fmaf(p.wxr, x, fmaf(p.uhr, h, p.br)));
            float ht = tanh_approx(fmaf(p.wxh, x,
                           fmaf(p.uhh, r * h, fmaf(p.vmh, m, p.bh))));

            h = fmaf(z, ht - h, h);

            __stcs(op + (size_t)(t0 + u) * FF, h);
        }
    };

    // ---- software pipeline: prefetch next batch before computing current ----
    load_batch(0, xa, ma, da);

    #pragma unroll 1
    for (int t0 = 0; t0 < TT; t0 += 2 * UNROLL) {
        // loads for batch B overlap compute of batch A
        load_batch(t0 + UNROLL, xb, mb, db);
        compute_batch(t0, xa, ma, da);

        // loads for next batch A overlap compute of batch B
        if (t0 + 2 * UNROLL < TT)
            load_batch(t0 + 2 * UNROLL, xa, ma, da);
        compute_batch(t0 + UNROLL, xb, mb, db);
    }

    if (out_last != nullptr) {
        out_last[(size_t)b * FF + f] = h;
    }
}

extern "C" void kernel_launch(void* const* d_in, const int* in_sizes, int n_in,
                              void* d_out, int out_size) {
    const float* X      = (const float*)d_in[0];
    const float* Mask   = (const float*)d_in[1];
    const float* Delta  = (const float*)d_in[2];
    const float* x_mean = (const float*)d_in[3];
    const float* w_dg_x = (const float*)d_in[4];
    const float* b_dg_x = (const float*)d_in[5];
    const float* w_dg_h = (const float*)d_in[6];
    const float* b_dg_h = (const float*)d_in[7];
    const float* w_xz   = (const float*)d_in[8];
    const float* u_hz   = (const float*)d_in[9];
    const float* b_z    = (const float*)d_in[10];
    const float* w_xr   = (const float*)d_in[11];
    const float* u_hr   = (const float*)d_in[12];
    const float* b_r    = (const float*)d_in[13];
    const float* w_xh   = (const float*)d_in[14];
    const float* u_hh   = (const float*)d_in[15];
    const float* v_mh   = (const float*)d_in[16];
    const float* b_h    = (const float*)d_in[17];

    float* out = (float*)d_out;
    const long long hs_elems = (long long)BB * TT * FF;
    float* out_last = ((long long)out_size >= hs_elems + (long long)BB * FF)
                          ? out + hs_elems : nullptr;

    grud_kernel<<<BF / BLK, BLK>>>(X, Mask, Delta, x_mean,
                                   w_dg_x, b_dg_x, w_dg_h, b_dg_h,
                                   w_xz, u_hz, b_z,
                                   w_xr, u_hr, b_r,
                                   w_xh, u_hh, v_mh, b_h,
                                   out, out_last);
}

// round 5
// speedup vs baseline: 2.0787x; 1.1414x over previous
#include <cuda_runtime.h>
#include <cstdint>

// GRU-D diagonal recurrence. One thread = one (b,f) chain, T=512 steps.
// R5: R4 schedule (depth-2 pipeline, period-3 slot rotation via x3-unrolled
// loop) with the output-stride bug fixed: inputs are [T,B,F] (t-stride BF),
// output is [B,T,F] (t-stride FF).

#define TT 512
#define BB 256
#define FF 256
#define BF (BB * FF)
#define UNROLL 8
#define NBATCH (TT / UNROLL)   // 64
#define BLK 64

__device__ __forceinline__ float tanh_approx(float v) {
    float r;
    asm("tanh.approx.f32 %0, %1;" : "=f"(r) : "f"(v));
    return r;
}
__device__ __forceinline__ float ex2_f(float v) {
    float r;
    asm("ex2.approx.f32 %0, %1;" : "=f"(r) : "f"(v));
    return r;
}

__global__ void __launch_bounds__(BLK) grud_kernel(
    const float* __restrict__ X,
    const float* __restrict__ Mask,
    const float* __restrict__ Delta,
    const float* __restrict__ x_mean,
    const float* __restrict__ w_dg_x, const float* __restrict__ b_dg_x,
    const float* __restrict__ w_dg_h, const float* __restrict__ b_dg_h,
    const float* __restrict__ w_xz,  const float* __restrict__ u_hz, const float* __restrict__ b_z,
    const float* __restrict__ w_xr,  const float* __restrict__ u_hr, const float* __restrict__ b_r,
    const float* __restrict__ w_xh,  const float* __restrict__ u_hh,
    const float* __restrict__ v_mh,  const float* __restrict__ b_h,
    float* __restrict__ out,        // [B, T, F]
    float* __restrict__ out_last)   // [B, F] or nullptr
{
    const int tid = blockIdx.x * BLK + threadIdx.x;
    const int f = tid & (FF - 1);
    const int b = tid >> 8;

    const float LOG2E = 1.4426950408889634f;

    // Per-feature params with constants folded in.
    const float xm    = x_mean[f];
    const float nwdgx = -LOG2E * w_dg_x[f], nbdgx = -LOG2E * b_dg_x[f];
    const float nwdgh = -LOG2E * w_dg_h[f], nbdgh = -LOG2E * b_dg_h[f];
    const float wxz2  = 0.5f * w_xz[f], uhz2 = 0.5f * u_hz[f], bz2 = 0.5f * b_z[f];
    const float wxr2  = 0.5f * w_xr[f], uhr2 = 0.5f * u_hr[f], br2 = 0.5f * b_r[f];
    const float wxh   = w_xh[f], uhh = u_hh[f];
    const float vmh   = v_mh[f], bh  = b_h[f];

    const float* xp = X     + (size_t)b * FF + f;   // [T,B,F]: t-stride = BF
    const float* mp = Mask  + (size_t)b * FF + f;
    const float* dp = Delta + (size_t)b * FF + f;
    float*       op = out   + (size_t)b * TT * FF + f;  // [B,T,F]: t-stride = FF

    float h = 0.0f;

    // 3 register buffers; all slot indices below are literal constants.
    float xv[3][UNROLL], mv[3][UNROLL], dv[3][UNROLL];

    auto load_batch = [&](int n, int s) {
        const float* xq = xp + (size_t)n * (BF * UNROLL);
        const float* mq = mp + (size_t)n * (BF * UNROLL);
        const float* dq = dp + (size_t)n * (BF * UNROLL);
        #pragma unroll
        for (int u = 0; u < UNROLL; ++u) {
            xv[s][u] = __ldcs(xq + u * BF);
            mv[s][u] = __ldcs(mq + u * BF);
            dv[s][u] = __ldcs(dq + u * BF);
        }
    };
    auto compute_batch = [&](int n, int s) {
        float* oq = op + (size_t)n * (FF * UNROLL);   // OUTPUT stride: FF per t
        #pragma unroll
        for (int u = 0; u < UNROLL; ++u) {
            float x = xv[s][u], m = mv[s][u], d = dv[s][u];

            // gamma = exp(-relu(w*d+b)) = ex2(min(0, fma(nw, d, nb)))
            float gx = ex2_f(fminf(0.0f, fmaf(nwdgx, d, nbdgx)));
            float gh = ex2_f(fminf(0.0f, fmaf(nwdgh, d, nbdgh)));

            // x = m*x + (1-m)*(gx*x + (1-gx)*xm)
            float ximp = fmaf(gx, x, (1.0f - gx) * xm);
            x = fmaf(m, x, (1.0f - m) * ximp);

            // h-independent partials (fill load shadow)
            float pz = fmaf(wxz2, x, bz2);
            float pr = fmaf(wxr2, x, br2);
            float ph = fmaf(wxh, x, fmaf(vmh, m, bh));

            h = gh * h;

            float z  = fmaf(0.5f, tanh_approx(fmaf(uhz2, h, pz)), 0.5f);
            float r  = fmaf(0.5f, tanh_approx(fmaf(uhr2, h, pr)), 0.5f);
            float ht = tanh_approx(fmaf(uhh, r * h, ph));

            h = fmaf(z, ht - h, h);

            __stcs(oq + u * FF, h);                   // OUTPUT stride: FF
        }
    };

    // Depth-2 pipeline, period-3 slot rotation via x3-unrolled loop.
    load_batch(0, 0);
    load_batch(1, 1);

    #pragma unroll 1
    for (int n = 0; n < NBATCH - 1; n += 3) {
        load_batch(n + 2, 2);
        compute_batch(n, 0);                        // slot0 free
        if (n + 3 < NBATCH) load_batch(n + 3, 0);
        compute_batch(n + 1, 1);                    // slot1 free
        if (n + 4 < NBATCH) load_batch(n + 4, 1);
        compute_batch(n + 2, 2);                    // slot2 free
    }
    // Batch 63 was loaded into slot0 during the n=60 iteration.
    compute_batch(NBATCH - 1, 0);

    if (out_last != nullptr) {
        out_last[(size_t)b * FF + f] = h;
    }
}

extern "C" void kernel_launch(void* const* d_in, const int* in_sizes, int n_in,
                              void* d_out, int out_size) {
    const float* X      = (const float*)d_in[0];
    const float* Mask   = (const float*)d_in[1];
    const float* Delta  = (const float*)d_in[2];
    const float* x_mean = (const float*)d_in[3];
    const float* w_dg_x = (const float*)d_in[4];
    const float* b_dg_x = (const float*)d_in[5];
    const float* w_dg_h = (const float*)d_in[6];
    const float* b_dg_h = (const float*)d_in[7];
    const float* w_xz   = (const float*)d_in[8];
    const float* u_hz   = (const float*)d_in[9];
    const float* b_z    = (const float*)d_in[10];
    const float* w_xr   = (const float*)d_in[11];
    const float* u_hr   = (const float*)d_in[12];
    const float* b_r    = (const float*)d_in[13];
    const float* w_xh   = (const float*)d_in[14];
    const float* u_hh   = (const float*)d_in[15];
    const float* v_mh   = (const float*)d_in[16];
    const float* b_h    = (const float*)d_in[17];

    float* out = (float*)d_out;
    const long long hs_elems = (long long)BB * TT * FF;
    float* out_last = ((long long)out_size >= hs_elems + (long long)BB * FF)
                          ? out + hs_elems : nullptr;

    grud_kernel<<<BF / BLK, BLK>>>(X, Mask, Delta, x_mean,
                                   w_dg_x, b_dg_x, w_dg_h, b_dg_h,
                                   w_xz, u_hz, b_z,
                                   w_xr, u_hr, b_r,
                                   w_xh, u_hh, v_mh, b_h,
                                   out, out_last);
}